// round 14
// baseline (speedup 1.0000x reference)
#include <cuda_runtime.h>
#include <cuda_fp16.h>
#include <cstdint>
#include <math.h>

// ---------------------------------------------------------------------------
// Problem constants
// ---------------------------------------------------------------------------
#define BATCH   16384
#define FDIM    256
#define NPAIRS  2016
#define K0      2272
#define K0P     2304          // padded to multiple of 64
#define D1      2048
#define D2      2048
#define D3      1024
#define BN_EPS  1e-5f
#define NSLAB   128           // BATCH / 128 M-slabs (one stats partial each)

// ---------------------------------------------------------------------------
// Scratch (static device arrays; runtime allocation forbidden)
// ---------------------------------------------------------------------------
__device__ __half g_H0[BATCH * (size_t)K0P];          // 75.5 MB
__device__ __half g_Zh[BATCH * (size_t)D1];           // 67 MB (L0/L1 preacts, fp16, reused)
__device__ __half g_A [BATCH * (size_t)D1];           // 67 MB (activations, reused L1/L2 inputs)
__device__ __half g_Z2[BATCH * (size_t)D3];           // 33.5 MB (L2 preacts, fp16)
__device__ __half g_W0[(size_t)D1 * K0P];
__device__ __half g_W1[(size_t)D2 * D1];
__device__ __half g_W2[(size_t)D3 * D2];
__device__ float g_PS[NSLAB * D1];
__device__ float g_PQ[NSLAB * D1];
__device__ float g_SCALE[D1];
__device__ float g_SHIFT[D1];
__device__ uchar2 g_PIJ[NPAIRS];                      // packed (i, j) per pair

// ---------------------------------------------------------------------------
// PTX wrappers (plain sm_80+ features)
// ---------------------------------------------------------------------------
__device__ __forceinline__ uint32_t smem_u32(const void* p) {
    uint32_t a;
    asm("{ .reg .u64 t; cvta.to.shared.u64 t, %1; cvt.u32.u64 %0, t; }" : "=r"(a) : "l"(p));
    return a;
}
__device__ __forceinline__ void cp16(uint32_t saddr, const void* gaddr) {
    asm volatile("cp.async.cg.shared.global [%0], [%1], 16;" :: "r"(saddr), "l"(gaddr));
}
__device__ __forceinline__ void ldsm_x4(uint32_t* r, uint32_t addr) {
    asm volatile("ldmatrix.sync.aligned.m8n8.x4.shared.b16 {%0,%1,%2,%3}, [%4];"
        : "=r"(r[0]), "=r"(r[1]), "=r"(r[2]), "=r"(r[3]) : "r"(addr));
}
__device__ __forceinline__ void mma16816(float* d, const uint32_t* a,
                                         uint32_t b0, uint32_t b1) {
    asm volatile(
        "mma.sync.aligned.m16n8k16.row.col.f32.f16.f16.f32 "
        "{%0,%1,%2,%3}, {%4,%5,%6,%7}, {%8,%9}, {%0,%1,%2,%3};"
        : "+f"(d[0]), "+f"(d[1]), "+f"(d[2]), "+f"(d[3])
        : "r"(a[0]), "r"(a[1]), "r"(a[2]), "r"(a[3]), "r"(b0), "r"(b1));
}

// ---------------------------------------------------------------------------
// Pair table (row-major upper triangle, k=1), packed uchar2
// ---------------------------------------------------------------------------
__global__ void build_pairs_kernel() {
    int p = blockIdx.x * blockDim.x + threadIdx.x;
    if (p >= NPAIRS) return;
    float disc = sqrtf(16129.0f - 8.0f * (float)p);
    int i = (int)((127.0f - disc) * 0.5f);
    while (((127 * (i + 1) - (i + 1) * (i + 1)) >> 1) <= p) i++;
    while (((127 * i - i * i) >> 1) > p) i--;
    int off = (127 * i - i * i) >> 1;
    int j = p - off + i + 1;
    g_PIJ[p] = make_uchar2((unsigned char)i, (unsigned char)j);
}

// ---------------------------------------------------------------------------
// H0 (fp16, zero-padded to K0P) — one block per batch row, vectorized
// ---------------------------------------------------------------------------
__global__ void __launch_bounds__(256) build_h0_kernel(const float* __restrict__ xv) {
    __shared__ float row[FDIM];
    int b = blockIdx.x;
    int tid = threadIdx.x;
    row[tid] = xv[(size_t)b * FDIM + tid];
    __syncthreads();
    __half* h = g_H0 + (size_t)b * K0P;
    h[tid] = __float2half_rn(row[tid]);
    const float inv255 = 1.0f / 255.0f;
    if (tid < NPAIRS / 8) {                             // 252 threads, 8 pairs each
        uint4 tbl = *(const uint4*)(g_PIJ + tid * 8);
        const unsigned char* ij = (const unsigned char*)&tbl;
        __half2 o[4];
        #pragma unroll
        for (int q = 0; q < 4; q++) {
            float v0 = row[ij[q * 4 + 0]] * row[ij[q * 4 + 1]] * inv255;
            float v1 = row[ij[q * 4 + 2]] * row[ij[q * 4 + 3]] * inv255;
            o[q] = __floats2half2_rn(v0, v1);
        }
        *(uint4*)(h + FDIM + tid * 8) = *(uint4*)o;
    } else if (tid < NPAIRS / 8 + 4) {                  // zero pad 2272..2303
        int q = tid - NPAIRS / 8;
        *(uint2*)(h + K0 + q * 8) = make_uint2(0u, 0u);
    }
}

// ---------------------------------------------------------------------------
// Weight convert/pad, 8 elems/thread: W fp32 [N, Kin] -> fp16 [N, Kout]
// ---------------------------------------------------------------------------
__global__ void __launch_bounds__(256) convert_w_kernel(
    const float* __restrict__ W, __half* __restrict__ Wh, int N, int Kin, int Kout)
{
    size_t i8 = (size_t)blockIdx.x * 256 + threadIdx.x;
    size_t total8 = (size_t)N * Kout / 8;
    if (i8 >= total8) return;
    int k = (int)((i8 * 8) % Kout);
    int n = (int)((i8 * 8) / Kout);
    __half2 o[4];
    if (k < Kin) {
        const float4* src = (const float4*)(W + (size_t)n * Kin + k);
        float4 v0 = src[0], v1 = src[1];
        o[0] = __floats2half2_rn(v0.x, v0.y);
        o[1] = __floats2half2_rn(v0.z, v0.w);
        o[2] = __floats2half2_rn(v1.x, v1.y);
        o[3] = __floats2half2_rn(v1.z, v1.w);
    } else {
        o[0] = o[1] = o[2] = o[3] = __floats2half2_rn(0.f, 0.f);
    }
    *(uint4*)(Wh + i8 * 8) = *(uint4*)o;
}

// ---------------------------------------------------------------------------
// fp16 mma.sync GEMM (fp16 output) with fused column stats.
// CHAMPION CONFIG: CTA 128x128, BK=64, 4 warps (2M x 2N), warp tile 64x64,
// 3-stage cp.async (wait_group 1), 96KB smem -> 2 CTAs/SM.
// ---------------------------------------------------------------------------
#define A_TILE_B 16384u
#define B_TILE_B 16384u
#define STAGE_B  (A_TILE_B + B_TILE_B)     // 32768
#define GEMM_SMEM (3u * STAGE_B)           // 98304

__device__ __forceinline__ void load_stage(
    uint32_t sbase, const __half* __restrict__ a, const __half* __restrict__ b,
    int kt, int K, int tid)
{
    const __half* ga = a + (size_t)kt * 64;
    #pragma unroll
    for (int i = 0; i < 8; i++) {
        int idx = tid + i * 128;            // 0..1023
        int row = idx >> 3;                 // 0..127
        int ch  = idx & 7;
        uint32_t off = (uint32_t)(row << 7) + (((uint32_t)ch << 4) ^ (((uint32_t)row & 7u) << 4));
        cp16(sbase + off, ga + (size_t)row * K + (ch << 3));
    }
    const __half* gb = b + (size_t)kt * 64;
    #pragma unroll
    for (int i = 0; i < 8; i++) {
        int idx = tid + i * 128;
        int row = idx >> 3;
        int ch  = idx & 7;
        uint32_t off = (uint32_t)(row << 7) + (((uint32_t)ch << 4) ^ (((uint32_t)row & 7u) << 4));
        cp16(sbase + A_TILE_B + off, gb + (size_t)row * K + (ch << 3));
    }
}

__global__ void __launch_bounds__(128, 2) gemm_f16_kernel(
    const __half* __restrict__ A, const __half* __restrict__ B,
    __half* __restrict__ C, int M, int N, int K)
{
    extern __shared__ char smraw[];
    const uint32_t smb = smem_u32(smraw);
    const int tid  = threadIdx.x;
    const int wid  = tid >> 5;
    const int lane = tid & 31;
    const int wm = wid & 1;
    const int wn = wid >> 1;
    const int bn = blockIdx.x, bm = blockIdx.y;
    const int T = K >> 6;

    const __half* a = A + (size_t)bm * 128 * K;
    const __half* b = B + (size_t)bn * 128 * K;

    float acc[4][8][4];
    #pragma unroll
    for (int x = 0; x < 4; x++)
        #pragma unroll
        for (int y = 0; y < 8; y++)
            #pragma unroll
            for (int z = 0; z < 4; z++) acc[x][y][z] = 0.0f;

    const int aRowBase = wm * 64 + (lane & 7) + ((lane >> 3) & 1) * 8;
    const uint32_t aKsel = ((lane >> 4) & 1) * 16;
    const int bRowBase = wn * 64 + ((lane >> 4) & 1) * 8 + (lane & 7);
    const uint32_t bKsel = ((lane >> 3) & 1) * 16;

    #pragma unroll
    for (int s = 0; s < 2; s++) {
        load_stage(smb + (uint32_t)s * STAGE_B, a, b, s, K, tid);
        asm volatile("cp.async.commit_group;" ::: "memory");
    }

    int buf = 0;
    for (int kt = 0; kt < T; kt++) {
        if (kt + 1 < T) asm volatile("cp.async.wait_group 1;" ::: "memory");
        else            asm volatile("cp.async.wait_group 0;" ::: "memory");
        __syncthreads();

        if (kt + 2 < T) {
            int nb = kt + 2 - 3 * ((kt + 2) / 3);
            load_stage(smb + (uint32_t)nb * STAGE_B, a, b, kt + 2, K, tid);
            asm volatile("cp.async.commit_group;" ::: "memory");
        }

        const uint32_t sA = smb + (uint32_t)buf * STAGE_B;
        const uint32_t sB = sA + A_TILE_B;

        #pragma unroll
        for (int kc = 0; kc < 4; kc++) {
            uint32_t fa[4][4];
            #pragma unroll
            for (int mf = 0; mf < 4; mf++) {
                int row = aRowBase + mf * 16;
                uint32_t kb = (uint32_t)kc * 32 + aKsel;
                uint32_t off = ((uint32_t)row << 7) + (kb ^ (((uint32_t)row & 7u) << 4));
                ldsm_x4(fa[mf], sA + off);
            }
            #pragma unroll
            for (int ng = 0; ng < 4; ng++) {
                uint32_t fb[4];
                int row = bRowBase + ng * 16;
                uint32_t kb = (uint32_t)kc * 32 + bKsel;
                uint32_t off = ((uint32_t)row << 7) + (kb ^ (((uint32_t)row & 7u) << 4));
                ldsm_x4(fb, sB + off);
                #pragma unroll
                for (int mf = 0; mf < 4; mf++) {
                    mma16816(acc[mf][ng * 2 + 0], fa[mf], fb[0], fb[1]);
                    mma16816(acc[mf][ng * 2 + 1], fa[mf], fb[2], fb[3]);
                }
            }
        }
        buf++;
        if (buf == 3) buf = 0;
        __syncthreads();
    }

    // ---- store C (fp16) ----
    const int r0 = bm * 128 + wm * 64 + (lane >> 2);
    const int c0 = bn * 128 + wn * 64 + (lane & 3) * 2;
    #pragma unroll
    for (int mf = 0; mf < 4; mf++) {
        #pragma unroll
        for (int nf = 0; nf < 8; nf++) {
            __half* p0 = C + (size_t)(r0 + mf * 16) * N + c0 + nf * 8;
            __half* p1 = C + (size_t)(r0 + mf * 16 + 8) * N + c0 + nf * 8;
            *(__half2*)p0 = __floats2half2_rn(acc[mf][nf][0], acc[mf][nf][1]);
            *(__half2*)p1 = __floats2half2_rn(acc[mf][nf][2], acc[mf][nf][3]);
        }
    }

    // ---- fused column stats over this CTA's 128 rows (fp32 accumulators) ----
    float se[8], so[8], qe[8], qo[8];
    #pragma unroll
    for (int nf = 0; nf < 8; nf++) {
        float s0 = 0.f, s1 = 0.f, q0 = 0.f, q1 = 0.f;
        #pragma unroll
        for (int mf = 0; mf < 4; mf++) {
            float a0 = acc[mf][nf][0], a1 = acc[mf][nf][1];
            float a2 = acc[mf][nf][2], a3 = acc[mf][nf][3];
            s0 += a0 + a2;  s1 += a1 + a3;
            q0 = fmaf(a0, a0, fmaf(a2, a2, q0));
            q1 = fmaf(a1, a1, fmaf(a3, a3, q1));
        }
        se[nf] = s0; so[nf] = s1; qe[nf] = q0; qo[nf] = q1;
    }
    #pragma unroll
    for (int off = 4; off <= 16; off <<= 1) {
        #pragma unroll
        for (int nf = 0; nf < 8; nf++) {
            se[nf] += __shfl_xor_sync(0xffffffffu, se[nf], off);
            so[nf] += __shfl_xor_sync(0xffffffffu, so[nf], off);
            qe[nf] += __shfl_xor_sync(0xffffffffu, qe[nf], off);
            qo[nf] += __shfl_xor_sync(0xffffffffu, qo[nf], off);
        }
    }
    float* ss = (float*)smraw;           // [2][128]
    float* sq = ss + 256;                // [2][128]
    if ((lane >> 2) == 0) {
        #pragma unroll
        for (int nf = 0; nf < 8; nf++) {
            int col = wn * 64 + nf * 8 + (lane & 3) * 2;
            ss[wm * 128 + col]     = se[nf];
            ss[wm * 128 + col + 1] = so[nf];
            sq[wm * 128 + col]     = qe[nf];
            sq[wm * 128 + col + 1] = qo[nf];
        }
    }
    __syncthreads();
    if (tid < 128) {
        g_PS[(size_t)bm * N + bn * 128 + tid] = ss[tid] + ss[128 + tid];
        g_PQ[(size_t)bm * N + bn * 128 + tid] = sq[tid] + sq[128 + tid];
    }
}

// ---------------------------------------------------------------------------
// BN finalize: reduce NSLAB partials -> per-column scale/shift
// ---------------------------------------------------------------------------
__global__ void __launch_bounds__(256) bn_finalize_kernel(
    const float* __restrict__ g, const float* __restrict__ be, int D)
{
    int col = blockIdx.x * 256 + threadIdx.x;
    if (col >= D) return;
    float s = 0.0f, q = 0.0f;
    #pragma unroll 8
    for (int c = 0; c < NSLAB; c++) { s += g_PS[c * D + col]; q += g_PQ[c * D + col]; }
    float invB = 1.0f / (float)BATCH;
    float mean = s * invB;
    float var  = q * invB - mean * mean;
    float sc   = g[col] / sqrtf(var + BN_EPS);
    g_SCALE[col] = sc;
    g_SHIFT[col] = be[col] - mean * sc;
}

// BN+ReLU: fp16 Z -> fp16 activations (out of place), 16 elems/thread
__global__ void __launch_bounds__(256) bn_relu_h2h_kernel(
    const __half* __restrict__ Z, __half* __restrict__ Ao, int D, int total16)
{
    int i = blockIdx.x * 256 + threadIdx.x;
    if (i >= total16) return;
    int col = (i * 16) % D;
    uint4 z0 = ((const uint4*)Z)[i * 2 + 0];
    uint4 z1 = ((const uint4*)Z)[i * 2 + 1];
    const __half2* h0 = (const __half2*)&z0;
    const __half2* h1 = (const __half2*)&z1;
    uint4 o0, o1;
    __half2* p0 = (__half2*)&o0;
    __half2* p1 = (__half2*)&o1;
    #pragma unroll
    for (int j = 0; j < 4; j++) {
        float2 f = __half22float2(h0[j]);
        int c = col + j * 2;
        p0[j] = __floats2half2_rn(fmaxf(0.f, fmaf(f.x, g_SCALE[c + 0], g_SHIFT[c + 0])),
                                  fmaxf(0.f, fmaf(f.y, g_SCALE[c + 1], g_SHIFT[c + 1])));
    }
    #pragma unroll
    for (int j = 0; j < 4; j++) {
        float2 f = __half22float2(h1[j]);
        int c = col + 8 + j * 2;
        p1[j] = __floats2half2_rn(fmaxf(0.f, fmaf(f.x, g_SCALE[c + 0], g_SHIFT[c + 0])),
                                  fmaxf(0.f, fmaf(f.y, g_SCALE[c + 1], g_SHIFT[c + 1])));
    }
    ((uint4*)Ao)[i * 2 + 0] = o0;
    ((uint4*)Ao)[i * 2 + 1] = o1;
}

// ---------------------------------------------------------------------------
// Fused BN+ReLU+GEMV head over fp16 raw preacts Z2:
//   out[b] = sum_k relu(Z2[b,k]*sc[k]+sh[k]) * Wout[k] + bout
// ---------------------------------------------------------------------------
__global__ void __launch_bounds__(256) out_bn_gemv_kernel(
    const __half* __restrict__ Z2, const float* __restrict__ Wout,
    const float* __restrict__ bout, float* __restrict__ out)
{
    __shared__ float w[D3], sc[D3], sh[D3];
    int tid = threadIdx.x;
    ((float4*)w)[tid]  = ((const float4*)Wout)[tid];
    ((float4*)sc)[tid] = ((const float4*)g_SCALE)[tid];
    ((float4*)sh)[tid] = ((const float4*)g_SHIFT)[tid];
    __syncthreads();
    int warp = tid >> 5, lane = tid & 31;
    int b = blockIdx.x * 8 + warp;
    const __half* a = Z2 + (size_t)b * D3;
    float sum = 0.0f;
    #pragma unroll
    for (int it = 0; it < 4; it++) {
        int k = it * 256 + lane * 8;
        uint4 zv = *(const uint4*)(a + k);
        const __half2* h = (const __half2*)&zv;
        #pragma unroll
        for (int j = 0; j < 4; j++) {
            float2 f = __half22float2(h[j]);
            int kk = k + j * 2;
            float y0 = fmaxf(0.0f, fmaf(f.x, sc[kk + 0], sh[kk + 0]));
            float y1 = fmaxf(0.0f, fmaf(f.y, sc[kk + 1], sh[kk + 1]));
            sum = fmaf(y0, w[kk + 0], sum);
            sum = fmaf(y1, w[kk + 1], sum);
        }
    }
    #pragma unroll
    for (int off = 16; off > 0; off >>= 1) sum += __shfl_down_sync(0xFFFFFFFFu, sum, off);
    if (lane == 0) out[b] = sum + bout[0];
}

// ---------------------------------------------------------------------------
// Host launcher. Inputs: 0 xv, 1 W0, 2 b0, 3 g0, 4 be0, 5 W1, 6 b1, 7 g1,
// 8 be1, 9 W2, 10 b2, 11 g2, 12 be2, 13 Wout, 14 bout.
// b0/b1/b2 are absorbed by train-mode BatchNorm and never read.
// ---------------------------------------------------------------------------
extern "C" void kernel_launch(void* const* d_in, const int* in_sizes, int n_in,
                              void* d_out, int out_size)
{
    const float* xv   = (const float*)d_in[0];
    const float* W0   = (const float*)d_in[1];
    const float* g0   = (const float*)d_in[3];
    const float* be0  = (const float*)d_in[4];
    const float* W1   = (const float*)d_in[5];
    const float* g1   = (const float*)d_in[7];
    const float* be1  = (const float*)d_in[8];
    const float* W2   = (const float*)d_in[9];
    const float* g2   = (const float*)d_in[11];
    const float* be2  = (const float*)d_in[12];
    const float* Wout = (const float*)d_in[13];
    const float* bout = (const float*)d_in[14];
    float* out = (float*)d_out;

    cudaFuncSetAttribute(gemm_f16_kernel, cudaFuncAttributeMaxDynamicSharedMemorySize, GEMM_SMEM);

    __half *H0, *Zh, *Ap, *Z2, *W0h, *W1h, *W2h;
    cudaGetSymbolAddress((void**)&H0,  g_H0);
    cudaGetSymbolAddress((void**)&Zh,  g_Zh);
    cudaGetSymbolAddress((void**)&Ap,  g_A);
    cudaGetSymbolAddress((void**)&Z2,  g_Z2);
    cudaGetSymbolAddress((void**)&W0h, g_W0);
    cudaGetSymbolAddress((void**)&W1h, g_W1);
    cudaGetSymbolAddress((void**)&W2h, g_W2);

    // frontend + weight prep
    build_pairs_kernel<<<8, 256>>>();
    build_h0_kernel<<<BATCH, 256>>>(xv);
    convert_w_kernel<<<(int)(((size_t)D1 * K0P / 8 + 255) / 256), 256>>>(W0, W0h, D1, K0, K0P);
    convert_w_kernel<<<(int)(((size_t)D2 * D1 / 8 + 255) / 256), 256>>>(W1, W1h, D2, D1, D1);
    convert_w_kernel<<<(int)(((size_t)D3 * D2 / 8 + 255) / 256), 256>>>(W2, W2h, D3, D2, D2);

    // layer 0: Zh = H0 @ W0^T (fp16, stats fused) -> BN+ReLU -> fp16 A
    gemm_f16_kernel<<<dim3(D1 / 128, BATCH / 128), 128, GEMM_SMEM>>>(H0, W0h, Zh, BATCH, D1, K0P);
    bn_finalize_kernel<<<D1 / 256, 256>>>(g0, be0, D1);
    bn_relu_h2h_kernel<<<(BATCH * D1 / 16) / 256, 256>>>(Zh, Ap, D1, BATCH * D1 / 16);

    // layer 1: Zh = A @ W1^T (fp16, stats fused) -> BN+ReLU -> fp16 A
    gemm_f16_kernel<<<dim3(D2 / 128, BATCH / 128), 128, GEMM_SMEM>>>(Ap, W1h, Zh, BATCH, D2, D1);
    bn_finalize_kernel<<<D2 / 256, 256>>>(g1, be1, D2);
    bn_relu_h2h_kernel<<<(BATCH * D2 / 16) / 256, 256>>>(Zh, Ap, D2, BATCH * D2 / 16);

    // layer 2: Z2 = A @ W2^T (fp16, stats fused) — BN folded into the head
    gemm_f16_kernel<<<dim3(D3 / 128, BATCH / 128), 128, GEMM_SMEM>>>(Ap, W2h, Z2, BATCH, D3, D2);
    bn_finalize_kernel<<<D3 / 256, 256>>>(g2, be2, D3);

    // fused BN2+ReLU+GEMV head
    out_bn_gemv_kernel<<<BATCH / 8, 256>>>(Z2, Wout, bout, out);
}

// round 15
// speedup vs baseline: 1.2053x; 1.2053x over previous
#include <cuda_runtime.h>
#include <cuda_fp16.h>
#include <cstdint>
#include <math.h>

// ---------------------------------------------------------------------------
// Problem constants
// ---------------------------------------------------------------------------
#define BATCH   16384
#define FDIM    256
#define NPAIRS  2016
#define K0      2272
#define K0P     2304          // padded to multiple of 64
#define D1      2048
#define D2      2048
#define D3      1024
#define BN_EPS  1e-5f
#define NSLAB   128           // BATCH / 128 M-slabs (one stats partial each)

// ---------------------------------------------------------------------------
// Scratch (static device arrays; runtime allocation forbidden)
// ---------------------------------------------------------------------------
__device__ __half g_H0[BATCH * (size_t)K0P];          // 75.5 MB
__device__ __half g_A [BATCH * (size_t)D1];           // 67 MB (activations, reused L1/L2 inputs)
__device__ float  g_Z [BATCH * (size_t)D1];           // 134 MB (L0/L1 preacts, fp32, reused)
__device__ __half g_Z2[BATCH * (size_t)D3];           // 33.5 MB (L2 preacts, fp16)
__device__ __half g_W0[(size_t)D1 * K0P];
__device__ __half g_W1[(size_t)D2 * D1];
__device__ __half g_W2[(size_t)D3 * D2];
__device__ float g_PS[NSLAB * D1];
__device__ float g_PQ[NSLAB * D1];
__device__ float g_SCALE[D1];
__device__ float g_SHIFT[D1];
__device__ uchar2 g_PIJ[NPAIRS];                      // packed (i, j) per pair

// ---------------------------------------------------------------------------
// PTX wrappers (plain sm_80+ features)
// ---------------------------------------------------------------------------
__device__ __forceinline__ uint32_t smem_u32(const void* p) {
    uint32_t a;
    asm("{ .reg .u64 t; cvta.to.shared.u64 t, %1; cvt.u32.u64 %0, t; }" : "=r"(a) : "l"(p));
    return a;
}
__device__ __forceinline__ void cp16(uint32_t saddr, const void* gaddr) {
    asm volatile("cp.async.cg.shared.global [%0], [%1], 16;" :: "r"(saddr), "l"(gaddr));
}
__device__ __forceinline__ void ldsm_x4(uint32_t* r, uint32_t addr) {
    asm volatile("ldmatrix.sync.aligned.m8n8.x4.shared.b16 {%0,%1,%2,%3}, [%4];"
        : "=r"(r[0]), "=r"(r[1]), "=r"(r[2]), "=r"(r[3]) : "r"(addr));
}
__device__ __forceinline__ void mma16816(float* d, const uint32_t* a,
                                         uint32_t b0, uint32_t b1) {
    asm volatile(
        "mma.sync.aligned.m16n8k16.row.col.f32.f16.f16.f32 "
        "{%0,%1,%2,%3}, {%4,%5,%6,%7}, {%8,%9}, {%0,%1,%2,%3};"
        : "+f"(d[0]), "+f"(d[1]), "+f"(d[2]), "+f"(d[3])
        : "r"(a[0]), "r"(a[1]), "r"(a[2]), "r"(a[3]), "r"(b0), "r"(b1));
}

// ---------------------------------------------------------------------------
// Pair table (row-major upper triangle, k=1), packed uchar2
// ---------------------------------------------------------------------------
__global__ void build_pairs_kernel() {
    int p = blockIdx.x * blockDim.x + threadIdx.x;
    if (p >= NPAIRS) return;
    float disc = sqrtf(16129.0f - 8.0f * (float)p);
    int i = (int)((127.0f - disc) * 0.5f);
    while (((127 * (i + 1) - (i + 1) * (i + 1)) >> 1) <= p) i++;
    while (((127 * i - i * i) >> 1) > p) i--;
    int off = (127 * i - i * i) >> 1;
    int j = p - off + i + 1;
    g_PIJ[p] = make_uchar2((unsigned char)i, (unsigned char)j);
}

// ---------------------------------------------------------------------------
// H0 (fp16, zero-padded to K0P) — one block per batch row, vectorized
// ---------------------------------------------------------------------------
__global__ void __launch_bounds__(256) build_h0_kernel(const float* __restrict__ xv) {
    __shared__ float row[FDIM];
    int b = blockIdx.x;
    int tid = threadIdx.x;
    row[tid] = xv[(size_t)b * FDIM + tid];
    __syncthreads();
    __half* h = g_H0 + (size_t)b * K0P;
    h[tid] = __float2half_rn(row[tid]);
    const float inv255 = 1.0f / 255.0f;
    if (tid < NPAIRS / 8) {                             // 252 threads, 8 pairs each
        uint4 tbl = *(const uint4*)(g_PIJ + tid * 8);
        const unsigned char* ij = (const unsigned char*)&tbl;
        __half2 o[4];
        #pragma unroll
        for (int q = 0; q < 4; q++) {
            float v0 = row[ij[q * 4 + 0]] * row[ij[q * 4 + 1]] * inv255;
            float v1 = row[ij[q * 4 + 2]] * row[ij[q * 4 + 3]] * inv255;
            o[q] = __floats2half2_rn(v0, v1);
        }
        *(uint4*)(h + FDIM + tid * 8) = *(uint4*)o;
    } else if (tid < NPAIRS / 8 + 4) {                  // zero pad 2272..2303
        int q = tid - NPAIRS / 8;
        *(uint2*)(h + K0 + q * 8) = make_uint2(0u, 0u);
    }
}

// ---------------------------------------------------------------------------
// Weight convert/pad, 8 elems/thread: W fp32 [N, Kin] -> fp16 [N, Kout]
// ---------------------------------------------------------------------------
__global__ void __launch_bounds__(256) convert_w_kernel(
    const float* __restrict__ W, __half* __restrict__ Wh, int N, int Kin, int Kout)
{
    size_t i8 = (size_t)blockIdx.x * 256 + threadIdx.x;
    size_t total8 = (size_t)N * Kout / 8;
    if (i8 >= total8) return;
    int k = (int)((i8 * 8) % Kout);
    int n = (int)((i8 * 8) / Kout);
    __half2 o[4];
    if (k < Kin) {
        const float4* src = (const float4*)(W + (size_t)n * Kin + k);
        float4 v0 = src[0], v1 = src[1];
        o[0] = __floats2half2_rn(v0.x, v0.y);
        o[1] = __floats2half2_rn(v0.z, v0.w);
        o[2] = __floats2half2_rn(v1.x, v1.y);
        o[3] = __floats2half2_rn(v1.z, v1.w);
    } else {
        o[0] = o[1] = o[2] = o[3] = __floats2half2_rn(0.f, 0.f);
    }
    *(uint4*)(Wh + i8 * 8) = *(uint4*)o;
}

// ---------------------------------------------------------------------------
// fp16 mma.sync GEMM (templated output dtype) with fused column stats.
// CHAMPION CONFIG: CTA 128x128, BK=64, 4 warps (2M x 2N), warp tile 64x64,
// 3-stage cp.async (wait_group 1), 96KB smem -> 2 CTAs/SM.
// ONE sync per kt: the top-of-iteration barrier already orders the prefetch
// into buffer (kt+2)%3 against its last readers (iteration kt-1).
// ---------------------------------------------------------------------------
#define A_TILE_B 16384u
#define B_TILE_B 16384u
#define STAGE_B  (A_TILE_B + B_TILE_B)     // 32768
#define GEMM_SMEM (3u * STAGE_B)           // 98304

__device__ __forceinline__ void load_stage(
    uint32_t sbase, const __half* __restrict__ a, const __half* __restrict__ b,
    int kt, int K, int tid)
{
    const __half* ga = a + (size_t)kt * 64;
    #pragma unroll
    for (int i = 0; i < 8; i++) {
        int idx = tid + i * 128;            // 0..1023
        int row = idx >> 3;                 // 0..127
        int ch  = idx & 7;
        uint32_t off = (uint32_t)(row << 7) + (((uint32_t)ch << 4) ^ (((uint32_t)row & 7u) << 4));
        cp16(sbase + off, ga + (size_t)row * K + (ch << 3));
    }
    const __half* gb = b + (size_t)kt * 64;
    #pragma unroll
    for (int i = 0; i < 8; i++) {
        int idx = tid + i * 128;
        int row = idx >> 3;
        int ch  = idx & 7;
        uint32_t off = (uint32_t)(row << 7) + (((uint32_t)ch << 4) ^ (((uint32_t)row & 7u) << 4));
        cp16(sbase + A_TILE_B + off, gb + (size_t)row * K + (ch << 3));
    }
}

template <typename OutT>
__device__ __forceinline__ void store_pair(OutT* p, float a0, float a1);
template <>
__device__ __forceinline__ void store_pair<float>(float* p, float a0, float a1) {
    *(float2*)p = make_float2(a0, a1);
}
template <>
__device__ __forceinline__ void store_pair<__half>(__half* p, float a0, float a1) {
    *(__half2*)p = __floats2half2_rn(a0, a1);
}

template <typename OutT>
__global__ void __launch_bounds__(128, 2) gemm_f16_kernel(
    const __half* __restrict__ A, const __half* __restrict__ B,
    OutT* __restrict__ C, int M, int N, int K)
{
    extern __shared__ char smraw[];
    const uint32_t smb = smem_u32(smraw);
    const int tid  = threadIdx.x;
    const int wid  = tid >> 5;
    const int lane = tid & 31;
    const int wm = wid & 1;
    const int wn = wid >> 1;
    const int bn = blockIdx.x, bm = blockIdx.y;
    const int T = K >> 6;

    const __half* a = A + (size_t)bm * 128 * K;
    const __half* b = B + (size_t)bn * 128 * K;

    float acc[4][8][4];
    #pragma unroll
    for (int x = 0; x < 4; x++)
        #pragma unroll
        for (int y = 0; y < 8; y++)
            #pragma unroll
            for (int z = 0; z < 4; z++) acc[x][y][z] = 0.0f;

    const int aRowBase = wm * 64 + (lane & 7) + ((lane >> 3) & 1) * 8;
    const uint32_t aKsel = ((lane >> 4) & 1) * 16;
    const int bRowBase = wn * 64 + ((lane >> 4) & 1) * 8 + (lane & 7);
    const uint32_t bKsel = ((lane >> 3) & 1) * 16;

    #pragma unroll
    for (int s = 0; s < 2; s++) {
        load_stage(smb + (uint32_t)s * STAGE_B, a, b, s, K, tid);
        asm volatile("cp.async.commit_group;" ::: "memory");
    }

    int buf = 0;
    for (int kt = 0; kt < T; kt++) {
        if (kt + 1 < T) asm volatile("cp.async.wait_group 1;" ::: "memory");
        else            asm volatile("cp.async.wait_group 0;" ::: "memory");
        __syncthreads();   // also orders this iteration's prefetch (below) after
                           // all warps' reads of that buffer in iteration kt-1

        if (kt + 2 < T) {
            int nb = kt + 2 - 3 * ((kt + 2) / 3);
            load_stage(smb + (uint32_t)nb * STAGE_B, a, b, kt + 2, K, tid);
            asm volatile("cp.async.commit_group;" ::: "memory");
        }

        const uint32_t sA = smb + (uint32_t)buf * STAGE_B;
        const uint32_t sB = sA + A_TILE_B;

        #pragma unroll
        for (int kc = 0; kc < 4; kc++) {
            uint32_t fa[4][4];
            #pragma unroll
            for (int mf = 0; mf < 4; mf++) {
                int row = aRowBase + mf * 16;
                uint32_t kb = (uint32_t)kc * 32 + aKsel;
                uint32_t off = ((uint32_t)row << 7) + (kb ^ (((uint32_t)row & 7u) << 4));
                ldsm_x4(fa[mf], sA + off);
            }
            #pragma unroll
            for (int ng = 0; ng < 4; ng++) {
                uint32_t fb[4];
                int row = bRowBase + ng * 16;
                uint32_t kb = (uint32_t)kc * 32 + bKsel;
                uint32_t off = ((uint32_t)row << 7) + (kb ^ (((uint32_t)row & 7u) << 4));
                ldsm_x4(fb, sB + off);
                #pragma unroll
                for (int mf = 0; mf < 4; mf++) {
                    mma16816(acc[mf][ng * 2 + 0], fa[mf], fb[0], fb[1]);
                    mma16816(acc[mf][ng * 2 + 1], fa[mf], fb[2], fb[3]);
                }
            }
        }
        buf++;
        if (buf == 3) buf = 0;
        // no trailing sync: next iteration's top barrier provides the ordering
    }
    __syncthreads();   // all mainloop smem reads done before stats staging reuse

    // ---- store C ----
    const int r0 = bm * 128 + wm * 64 + (lane >> 2);
    const int c0 = bn * 128 + wn * 64 + (lane & 3) * 2;
    #pragma unroll
    for (int mf = 0; mf < 4; mf++) {
        #pragma unroll
        for (int nf = 0; nf < 8; nf++) {
            OutT* p0 = C + (size_t)(r0 + mf * 16) * N + c0 + nf * 8;
            OutT* p1 = C + (size_t)(r0 + mf * 16 + 8) * N + c0 + nf * 8;
            store_pair<OutT>(p0, acc[mf][nf][0], acc[mf][nf][1]);
            store_pair<OutT>(p1, acc[mf][nf][2], acc[mf][nf][3]);
        }
    }

    // ---- fused column stats over this CTA's 128 rows (fp32 accumulators) ----
    float se[8], so[8], qe[8], qo[8];
    #pragma unroll
    for (int nf = 0; nf < 8; nf++) {
        float s0 = 0.f, s1 = 0.f, q0 = 0.f, q1 = 0.f;
        #pragma unroll
        for (int mf = 0; mf < 4; mf++) {
            float a0 = acc[mf][nf][0], a1 = acc[mf][nf][1];
            float a2 = acc[mf][nf][2], a3 = acc[mf][nf][3];
            s0 += a0 + a2;  s1 += a1 + a3;
            q0 = fmaf(a0, a0, fmaf(a2, a2, q0));
            q1 = fmaf(a1, a1, fmaf(a3, a3, q1));
        }
        se[nf] = s0; so[nf] = s1; qe[nf] = q0; qo[nf] = q1;
    }
    #pragma unroll
    for (int off = 4; off <= 16; off <<= 1) {
        #pragma unroll
        for (int nf = 0; nf < 8; nf++) {
            se[nf] += __shfl_xor_sync(0xffffffffu, se[nf], off);
            so[nf] += __shfl_xor_sync(0xffffffffu, so[nf], off);
            qe[nf] += __shfl_xor_sync(0xffffffffu, qe[nf], off);
            qo[nf] += __shfl_xor_sync(0xffffffffu, qo[nf], off);
        }
    }
    float* ss = (float*)smraw;           // [2][128]
    float* sq = ss + 256;                // [2][128]
    if ((lane >> 2) == 0) {
        #pragma unroll
        for (int nf = 0; nf < 8; nf++) {
            int col = wn * 64 + nf * 8 + (lane & 3) * 2;
            ss[wm * 128 + col]     = se[nf];
            ss[wm * 128 + col + 1] = so[nf];
            sq[wm * 128 + col]     = qe[nf];
            sq[wm * 128 + col + 1] = qo[nf];
        }
    }
    __syncthreads();
    if (tid < 128) {
        g_PS[(size_t)bm * N + bn * 128 + tid] = ss[tid] + ss[128 + tid];
        g_PQ[(size_t)bm * N + bn * 128 + tid] = sq[tid] + sq[128 + tid];
    }
}

// ---------------------------------------------------------------------------
// BN finalize: reduce NSLAB partials -> per-column scale/shift
// ---------------------------------------------------------------------------
__global__ void __launch_bounds__(256) bn_finalize_kernel(
    const float* __restrict__ g, const float* __restrict__ be, int D)
{
    int col = blockIdx.x * 256 + threadIdx.x;
    if (col >= D) return;
    float s = 0.0f, q = 0.0f;
    #pragma unroll 8
    for (int c = 0; c < NSLAB; c++) { s += g_PS[c * D + col]; q += g_PQ[c * D + col]; }
    float invB = 1.0f / (float)BATCH;
    float mean = s * invB;
    float var  = q * invB - mean * mean;
    float sc   = g[col] / sqrtf(var + BN_EPS);
    g_SCALE[col] = sc;
    g_SHIFT[col] = be[col] - mean * sc;
}

// BN+ReLU: fp32 Z -> fp16 activations, 8 outputs/thread
__global__ void __launch_bounds__(256) bn_relu_half_kernel(
    const float* __restrict__ Z, __half* __restrict__ Ao, int D, int total8)
{
    int i = blockIdx.x * 256 + threadIdx.x;
    if (i >= total8) return;
    int col = (i * 8) % D;
    float4 v0 = ((const float4*)Z)[i * 2 + 0];
    float4 v1 = ((const float4*)Z)[i * 2 + 1];
    float4 sc0 = *(const float4*)&g_SCALE[col];
    float4 sc1 = *(const float4*)&g_SCALE[col + 4];
    float4 sh0 = *(const float4*)&g_SHIFT[col];
    float4 sh1 = *(const float4*)&g_SHIFT[col + 4];
    __half2 o[4];
    o[0] = __floats2half2_rn(fmaxf(0.f, fmaf(v0.x, sc0.x, sh0.x)),
                             fmaxf(0.f, fmaf(v0.y, sc0.y, sh0.y)));
    o[1] = __floats2half2_rn(fmaxf(0.f, fmaf(v0.z, sc0.z, sh0.z)),
                             fmaxf(0.f, fmaf(v0.w, sc0.w, sh0.w)));
    o[2] = __floats2half2_rn(fmaxf(0.f, fmaf(v1.x, sc1.x, sh1.x)),
                             fmaxf(0.f, fmaf(v1.y, sc1.y, sh1.y)));
    o[3] = __floats2half2_rn(fmaxf(0.f, fmaf(v1.z, sc1.z, sh1.z)),
                             fmaxf(0.f, fmaf(v1.w, sc1.w, sh1.w)));
    ((uint4*)Ao)[i] = *(uint4*)o;
}

// ---------------------------------------------------------------------------
// Fused BN+ReLU+GEMV head over fp16 raw preacts Z2:
//   out[b] = sum_k relu(Z2[b,k]*sc[k]+sh[k]) * Wout[k] + bout
// ---------------------------------------------------------------------------
__global__ void __launch_bounds__(256) out_bn_gemv_kernel(
    const __half* __restrict__ Z2, const float* __restrict__ Wout,
    const float* __restrict__ bout, float* __restrict__ out)
{
    __shared__ float w[D3], sc[D3], sh[D3];
    int tid = threadIdx.x;
    ((float4*)w)[tid]  = ((const float4*)Wout)[tid];
    ((float4*)sc)[tid] = ((const float4*)g_SCALE)[tid];
    ((float4*)sh)[tid] = ((const float4*)g_SHIFT)[tid];
    __syncthreads();
    int warp = tid >> 5, lane = tid & 31;
    int b = blockIdx.x * 8 + warp;
    const __half* a = Z2 + (size_t)b * D3;
    float sum = 0.0f;
    #pragma unroll
    for (int it = 0; it < 4; it++) {
        int k = it * 256 + lane * 8;
        uint4 zv = *(const uint4*)(a + k);
        const __half2* h = (const __half2*)&zv;
        #pragma unroll
        for (int j = 0; j < 4; j++) {
            float2 f = __half22float2(h[j]);
            int kk = k + j * 2;
            float y0 = fmaxf(0.0f, fmaf(f.x, sc[kk + 0], sh[kk + 0]));
            float y1 = fmaxf(0.0f, fmaf(f.y, sc[kk + 1], sh[kk + 1]));
            sum = fmaf(y0, w[kk + 0], sum);
            sum = fmaf(y1, w[kk + 1], sum);
        }
    }
    #pragma unroll
    for (int off = 16; off > 0; off >>= 1) sum += __shfl_down_sync(0xFFFFFFFFu, sum, off);
    if (lane == 0) out[b] = sum + bout[0];
}

// ---------------------------------------------------------------------------
// Host launcher. Inputs: 0 xv, 1 W0, 2 b0, 3 g0, 4 be0, 5 W1, 6 b1, 7 g1,
// 8 be1, 9 W2, 10 b2, 11 g2, 12 be2, 13 Wout, 14 bout.
// b0/b1/b2 are absorbed by train-mode BatchNorm and never read.
// ---------------------------------------------------------------------------
extern "C" void kernel_launch(void* const* d_in, const int* in_sizes, int n_in,
                              void* d_out, int out_size)
{
    const float* xv   = (const float*)d_in[0];
    const float* W0   = (const float*)d_in[1];
    const float* g0   = (const float*)d_in[3];
    const float* be0  = (const float*)d_in[4];
    const float* W1   = (const float*)d_in[5];
    const float* g1   = (const float*)d_in[7];
    const float* be1  = (const float*)d_in[8];
    const float* W2   = (const float*)d_in[9];
    const float* g2   = (const float*)d_in[11];
    const float* be2  = (const float*)d_in[12];
    const float* Wout = (const float*)d_in[13];
    const float* bout = (const float*)d_in[14];
    float* out = (float*)d_out;

    cudaFuncSetAttribute(gemm_f16_kernel<float>,  cudaFuncAttributeMaxDynamicSharedMemorySize, GEMM_SMEM);
    cudaFuncSetAttribute(gemm_f16_kernel<__half>, cudaFuncAttributeMaxDynamicSharedMemorySize, GEMM_SMEM);

    __half *H0, *Ap, *Z2, *W0h, *W1h, *W2h;
    float *Z;
    cudaGetSymbolAddress((void**)&H0,  g_H0);
    cudaGetSymbolAddress((void**)&Ap,  g_A);
    cudaGetSymbolAddress((void**)&Z,   g_Z);
    cudaGetSymbolAddress((void**)&Z2,  g_Z2);
    cudaGetSymbolAddress((void**)&W0h, g_W0);
    cudaGetSymbolAddress((void**)&W1h, g_W1);
    cudaGetSymbolAddress((void**)&W2h, g_W2);

    // frontend + weight prep
    build_pairs_kernel<<<8, 256>>>();
    build_h0_kernel<<<BATCH, 256>>>(xv);
    convert_w_kernel<<<(int)(((size_t)D1 * K0P / 8 + 255) / 256), 256>>>(W0, W0h, D1, K0, K0P);
    convert_w_kernel<<<(int)(((size_t)D2 * D1 / 8 + 255) / 256), 256>>>(W1, W1h, D2, D1, D1);
    convert_w_kernel<<<(int)(((size_t)D3 * D2 / 8 + 255) / 256), 256>>>(W2, W2h, D3, D2, D2);

    // layer 0: Z = H0 @ W0^T (fp32, stats fused) -> BN+ReLU -> fp16 A
    gemm_f16_kernel<float><<<dim3(D1 / 128, BATCH / 128), 128, GEMM_SMEM>>>(H0, W0h, Z, BATCH, D1, K0P);
    bn_finalize_kernel<<<D1 / 256, 256>>>(g0, be0, D1);
    bn_relu_half_kernel<<<(BATCH * D1 / 8) / 256, 256>>>(Z, Ap, D1, BATCH * D1 / 8);

    // layer 1: Z = A @ W1^T (fp32, stats fused) -> BN+ReLU -> fp16 A
    gemm_f16_kernel<float><<<dim3(D2 / 128, BATCH / 128), 128, GEMM_SMEM>>>(Ap, W1h, Z, BATCH, D2, D1);
    bn_finalize_kernel<<<D2 / 256, 256>>>(g1, be1, D2);
    bn_relu_half_kernel<<<(BATCH * D2 / 8) / 256, 256>>>(Z, Ap, D2, BATCH * D2 / 8);

    // layer 2: Z2 = A @ W2^T (fp16 out, stats fused) — BN folded into the head
    gemm_f16_kernel<__half><<<dim3(D3 / 128, BATCH / 128), 128, GEMM_SMEM>>>(Ap, W2h, Z2, BATCH, D3, D2);
    bn_finalize_kernel<<<D3 / 256, 256>>>(g2, be2, D3);

    // fused BN2+ReLU+GEMV head
    out_bn_gemv_kernel<<<BATCH / 8, 256>>>(Z2, Wout, bout, out);
}

// round 16
// speedup vs baseline: 1.2119x; 1.0055x over previous
#include <cuda_runtime.h>
#include <cuda_fp16.h>
#include <cstdint>
#include <math.h>

// ---------------------------------------------------------------------------
// Problem constants
// ---------------------------------------------------------------------------
#define BATCH   16384
#define FDIM    256
#define NPAIRS  2016
#define K0      2272
#define K0P     2304          // padded to multiple of 64
#define D1      2048
#define D2      2048
#define D3      1024
#define BN_EPS  1e-5f
#define NSLAB   128           // BATCH / 128 M-slabs (one stats partial each)

// ---------------------------------------------------------------------------
// Scratch (static device arrays; runtime allocation forbidden)
// ---------------------------------------------------------------------------
__device__ __half g_H0[BATCH * (size_t)K0P];          // 75.5 MB
__device__ __half g_A [BATCH * (size_t)D1];           // 67 MB (activations, reused L1/L2 inputs)
__device__ float  g_Z [BATCH * (size_t)D1];           // 134 MB (L0/L1 preacts, fp32, reused)
__device__ __half g_Z2[BATCH * (size_t)D3];           // 33.5 MB (L2 preacts, fp16)
__device__ __half g_W0[(size_t)D1 * K0P];
__device__ __half g_W1[(size_t)D2 * D1];
__device__ __half g_W2[(size_t)D3 * D2];
__device__ float g_PS[NSLAB * D1];
__device__ float g_PQ[NSLAB * D1];
__device__ float g_SCALE[D1];
__device__ float g_SHIFT[D1];
__device__ uchar2 g_PIJ[NPAIRS];                      // packed (i, j) per pair

// ---------------------------------------------------------------------------
// PTX wrappers (plain sm_80+ features)
// ---------------------------------------------------------------------------
__device__ __forceinline__ uint32_t smem_u32(const void* p) {
    uint32_t a;
    asm("{ .reg .u64 t; cvta.to.shared.u64 t, %1; cvt.u32.u64 %0, t; }" : "=r"(a) : "l"(p));
    return a;
}
__device__ __forceinline__ void cp16(uint32_t saddr, const void* gaddr) {
    asm volatile("cp.async.cg.shared.global [%0], [%1], 16;" :: "r"(saddr), "l"(gaddr));
}
__device__ __forceinline__ void ldsm_x4(uint32_t* r, uint32_t addr) {
    asm volatile("ldmatrix.sync.aligned.m8n8.x4.shared.b16 {%0,%1,%2,%3}, [%4];"
        : "=r"(r[0]), "=r"(r[1]), "=r"(r[2]), "=r"(r[3]) : "r"(addr));
}
__device__ __forceinline__ void mma16816(float* d, const uint32_t* a,
                                         uint32_t b0, uint32_t b1) {
    asm volatile(
        "mma.sync.aligned.m16n8k16.row.col.f32.f16.f16.f32 "
        "{%0,%1,%2,%3}, {%4,%5,%6,%7}, {%8,%9}, {%0,%1,%2,%3};"
        : "+f"(d[0]), "+f"(d[1]), "+f"(d[2]), "+f"(d[3])
        : "r"(a[0]), "r"(a[1]), "r"(a[2]), "r"(a[3]), "r"(b0), "r"(b1));
}

// ---------------------------------------------------------------------------
// Pair table (row-major upper triangle, k=1), packed uchar2
// ---------------------------------------------------------------------------
__global__ void build_pairs_kernel() {
    int p = blockIdx.x * blockDim.x + threadIdx.x;
    if (p >= NPAIRS) return;
    float disc = sqrtf(16129.0f - 8.0f * (float)p);
    int i = (int)((127.0f - disc) * 0.5f);
    while (((127 * (i + 1) - (i + 1) * (i + 1)) >> 1) <= p) i++;
    while (((127 * i - i * i) >> 1) > p) i--;
    int off = (127 * i - i * i) >> 1;
    int j = p - off + i + 1;
    g_PIJ[p] = make_uchar2((unsigned char)i, (unsigned char)j);
}

// ---------------------------------------------------------------------------
// H0 (fp16, zero-padded to K0P) — one block per batch row, vectorized
// ---------------------------------------------------------------------------
__global__ void __launch_bounds__(256) build_h0_kernel(const float* __restrict__ xv) {
    __shared__ float row[FDIM];
    int b = blockIdx.x;
    int tid = threadIdx.x;
    row[tid] = xv[(size_t)b * FDIM + tid];
    __syncthreads();
    __half* h = g_H0 + (size_t)b * K0P;
    h[tid] = __float2half_rn(row[tid]);
    const float inv255 = 1.0f / 255.0f;
    if (tid < NPAIRS / 8) {                             // 252 threads, 8 pairs each
        uint4 tbl = *(const uint4*)(g_PIJ + tid * 8);
        const unsigned char* ij = (const unsigned char*)&tbl;
        __half2 o[4];
        #pragma unroll
        for (int q = 0; q < 4; q++) {
            float v0 = row[ij[q * 4 + 0]] * row[ij[q * 4 + 1]] * inv255;
            float v1 = row[ij[q * 4 + 2]] * row[ij[q * 4 + 3]] * inv255;
            o[q] = __floats2half2_rn(v0, v1);
        }
        *(uint4*)(h + FDIM + tid * 8) = *(uint4*)o;
    } else if (tid < NPAIRS / 8 + 4) {                  // zero pad 2272..2303
        int q = tid - NPAIRS / 8;
        *(uint2*)(h + K0 + q * 8) = make_uint2(0u, 0u);
    }
}

// ---------------------------------------------------------------------------
// Weight convert/pad, 8 elems/thread: W fp32 [N, Kin] -> fp16 [N, Kout]
// ---------------------------------------------------------------------------
__global__ void __launch_bounds__(256) convert_w_kernel(
    const float* __restrict__ W, __half* __restrict__ Wh, int N, int Kin, int Kout)
{
    size_t i8 = (size_t)blockIdx.x * 256 + threadIdx.x;
    size_t total8 = (size_t)N * Kout / 8;
    if (i8 >= total8) return;
    int k = (int)((i8 * 8) % Kout);
    int n = (int)((i8 * 8) / Kout);
    __half2 o[4];
    if (k < Kin) {
        const float4* src = (const float4*)(W + (size_t)n * Kin + k);
        float4 v0 = src[0], v1 = src[1];
        o[0] = __floats2half2_rn(v0.x, v0.y);
        o[1] = __floats2half2_rn(v0.z, v0.w);
        o[2] = __floats2half2_rn(v1.x, v1.y);
        o[3] = __floats2half2_rn(v1.z, v1.w);
    } else {
        o[0] = o[1] = o[2] = o[3] = __floats2half2_rn(0.f, 0.f);
    }
    *(uint4*)(Wh + i8 * 8) = *(uint4*)o;
}

// ---------------------------------------------------------------------------
// fp16 mma.sync GEMM (templated output dtype) with fused column stats.
// CHAMPION CONFIG: CTA 128x128, BK=64, 4 warps (2M x 2N), warp tile 64x64,
// 3-stage cp.async (wait_group 1), 96KB smem -> 2 CTAs/SM, one sync per kt.
// ---------------------------------------------------------------------------
#define A_TILE_B 16384u
#define B_TILE_B 16384u
#define STAGE_B  (A_TILE_B + B_TILE_B)     // 32768
#define GEMM_SMEM (3u * STAGE_B)           // 98304

__device__ __forceinline__ void load_stage(
    uint32_t sbase, const __half* __restrict__ a, const __half* __restrict__ b,
    int kt, int K, int tid)
{
    const __half* ga = a + (size_t)kt * 64;
    #pragma unroll
    for (int i = 0; i < 8; i++) {
        int idx = tid + i * 128;            // 0..1023
        int row = idx >> 3;                 // 0..127
        int ch  = idx & 7;
        uint32_t off = (uint32_t)(row << 7) + (((uint32_t)ch << 4) ^ (((uint32_t)row & 7u) << 4));
        cp16(sbase + off, ga + (size_t)row * K + (ch << 3));
    }
    const __half* gb = b + (size_t)kt * 64;
    #pragma unroll
    for (int i = 0; i < 8; i++) {
        int idx = tid + i * 128;
        int row = idx >> 3;
        int ch  = idx & 7;
        uint32_t off = (uint32_t)(row << 7) + (((uint32_t)ch << 4) ^ (((uint32_t)row & 7u) << 4));
        cp16(sbase + A_TILE_B + off, gb + (size_t)row * K + (ch << 3));
    }
}

template <typename OutT>
__device__ __forceinline__ void store_pair(OutT* p, float a0, float a1);
template <>
__device__ __forceinline__ void store_pair<float>(float* p, float a0, float a1) {
    *(float2*)p = make_float2(a0, a1);
}
template <>
__device__ __forceinline__ void store_pair<__half>(__half* p, float a0, float a1) {
    *(__half2*)p = __floats2half2_rn(a0, a1);
}

template <typename OutT>
__global__ void __launch_bounds__(128, 2) gemm_f16_kernel(
    const __half* __restrict__ A, const __half* __restrict__ B,
    OutT* __restrict__ C, int M, int N, int K)
{
    extern __shared__ char smraw[];
    const uint32_t smb = smem_u32(smraw);
    const int tid  = threadIdx.x;
    const int wid  = tid >> 5;
    const int lane = tid & 31;
    const int wm = wid & 1;
    const int wn = wid >> 1;
    const int bn = blockIdx.x, bm = blockIdx.y;
    const int T = K >> 6;

    const __half* a = A + (size_t)bm * 128 * K;
    const __half* b = B + (size_t)bn * 128 * K;

    float acc[4][8][4];
    #pragma unroll
    for (int x = 0; x < 4; x++)
        #pragma unroll
        for (int y = 0; y < 8; y++)
            #pragma unroll
            for (int z = 0; z < 4; z++) acc[x][y][z] = 0.0f;

    const int aRowBase = wm * 64 + (lane & 7) + ((lane >> 3) & 1) * 8;
    const uint32_t aKsel = ((lane >> 4) & 1) * 16;
    const int bRowBase = wn * 64 + ((lane >> 4) & 1) * 8 + (lane & 7);
    const uint32_t bKsel = ((lane >> 3) & 1) * 16;

    #pragma unroll
    for (int s = 0; s < 2; s++) {
        load_stage(smb + (uint32_t)s * STAGE_B, a, b, s, K, tid);
        asm volatile("cp.async.commit_group;" ::: "memory");
    }

    int buf = 0;
    for (int kt = 0; kt < T; kt++) {
        if (kt + 1 < T) asm volatile("cp.async.wait_group 1;" ::: "memory");
        else            asm volatile("cp.async.wait_group 0;" ::: "memory");
        __syncthreads();   // also orders this iteration's prefetch (below) after
                           // all warps' reads of that buffer in iteration kt-1

        if (kt + 2 < T) {
            int nb = kt + 2 - 3 * ((kt + 2) / 3);
            load_stage(smb + (uint32_t)nb * STAGE_B, a, b, kt + 2, K, tid);
            asm volatile("cp.async.commit_group;" ::: "memory");
        }

        const uint32_t sA = smb + (uint32_t)buf * STAGE_B;
        const uint32_t sB = sA + A_TILE_B;

        #pragma unroll
        for (int kc = 0; kc < 4; kc++) {
            uint32_t fa[4][4];
            #pragma unroll
            for (int mf = 0; mf < 4; mf++) {
                int row = aRowBase + mf * 16;
                uint32_t kb = (uint32_t)kc * 32 + aKsel;
                uint32_t off = ((uint32_t)row << 7) + (kb ^ (((uint32_t)row & 7u) << 4));
                ldsm_x4(fa[mf], sA + off);
            }
            #pragma unroll
            for (int ng = 0; ng < 4; ng++) {
                uint32_t fb[4];
                int row = bRowBase + ng * 16;
                uint32_t kb = (uint32_t)kc * 32 + bKsel;
                uint32_t off = ((uint32_t)row << 7) + (kb ^ (((uint32_t)row & 7u) << 4));
                ldsm_x4(fb, sB + off);
                #pragma unroll
                for (int mf = 0; mf < 4; mf++) {
                    mma16816(acc[mf][ng * 2 + 0], fa[mf], fb[0], fb[1]);
                    mma16816(acc[mf][ng * 2 + 1], fa[mf], fb[2], fb[3]);
                }
            }
        }
        buf++;
        if (buf == 3) buf = 0;
        // no trailing sync: next iteration's top barrier provides the ordering
    }
    __syncthreads();   // all mainloop smem reads done before stats staging reuse

    // ---- store C ----
    const int r0 = bm * 128 + wm * 64 + (lane >> 2);
    const int c0 = bn * 128 + wn * 64 + (lane & 3) * 2;
    #pragma unroll
    for (int mf = 0; mf < 4; mf++) {
        #pragma unroll
        for (int nf = 0; nf < 8; nf++) {
            OutT* p0 = C + (size_t)(r0 + mf * 16) * N + c0 + nf * 8;
            OutT* p1 = C + (size_t)(r0 + mf * 16 + 8) * N + c0 + nf * 8;
            store_pair<OutT>(p0, acc[mf][nf][0], acc[mf][nf][1]);
            store_pair<OutT>(p1, acc[mf][nf][2], acc[mf][nf][3]);
        }
    }

    // ---- fused column stats over this CTA's 128 rows (fp32 accumulators) ----
    float se[8], so[8], qe[8], qo[8];
    #pragma unroll
    for (int nf = 0; nf < 8; nf++) {
        float s0 = 0.f, s1 = 0.f, q0 = 0.f, q1 = 0.f;
        #pragma unroll
        for (int mf = 0; mf < 4; mf++) {
            float a0 = acc[mf][nf][0], a1 = acc[mf][nf][1];
            float a2 = acc[mf][nf][2], a3 = acc[mf][nf][3];
            s0 += a0 + a2;  s1 += a1 + a3;
            q0 = fmaf(a0, a0, fmaf(a2, a2, q0));
            q1 = fmaf(a1, a1, fmaf(a3, a3, q1));
        }
        se[nf] = s0; so[nf] = s1; qe[nf] = q0; qo[nf] = q1;
    }
    #pragma unroll
    for (int off = 4; off <= 16; off <<= 1) {
        #pragma unroll
        for (int nf = 0; nf < 8; nf++) {
            se[nf] += __shfl_xor_sync(0xffffffffu, se[nf], off);
            so[nf] += __shfl_xor_sync(0xffffffffu, so[nf], off);
            qe[nf] += __shfl_xor_sync(0xffffffffu, qe[nf], off);
            qo[nf] += __shfl_xor_sync(0xffffffffu, qo[nf], off);
        }
    }
    float* ss = (float*)smraw;           // [2][128]
    float* sq = ss + 256;                // [2][128]
    if ((lane >> 2) == 0) {
        #pragma unroll
        for (int nf = 0; nf < 8; nf++) {
            int col = wn * 64 + nf * 8 + (lane & 3) * 2;
            ss[wm * 128 + col]     = se[nf];
            ss[wm * 128 + col + 1] = so[nf];
            sq[wm * 128 + col]     = qe[nf];
            sq[wm * 128 + col + 1] = qo[nf];
        }
    }
    __syncthreads();
    if (tid < 128) {
        g_PS[(size_t)bm * N + bn * 128 + tid] = ss[tid] + ss[128 + tid];
        g_PQ[(size_t)bm * N + bn * 128 + tid] = sq[tid] + sq[128 + tid];
    }
}

// ---------------------------------------------------------------------------
// BN finalize: reduce NSLAB partials -> per-column scale/shift
// ---------------------------------------------------------------------------
__global__ void __launch_bounds__(256) bn_finalize_kernel(
    const float* __restrict__ g, const float* __restrict__ be, int D)
{
    int col = blockIdx.x * 256 + threadIdx.x;
    if (col >= D) return;
    float s = 0.0f, q = 0.0f;
    #pragma unroll 8
    for (int c = 0; c < NSLAB; c++) { s += g_PS[c * D + col]; q += g_PQ[c * D + col]; }
    float invB = 1.0f / (float)BATCH;
    float mean = s * invB;
    float var  = q * invB - mean * mean;
    float sc   = g[col] / sqrtf(var + BN_EPS);
    g_SCALE[col] = sc;
    g_SHIFT[col] = be[col] - mean * sc;
}

// BN+ReLU: fp32 Z -> fp16 activations, 8 outputs/thread
__global__ void __launch_bounds__(256) bn_relu_half_kernel(
    const float* __restrict__ Z, __half* __restrict__ Ao, int D, int total8)
{
    int i = blockIdx.x * 256 + threadIdx.x;
    if (i >= total8) return;
    int col = (i * 8) % D;
    float4 v0 = ((const float4*)Z)[i * 2 + 0];
    float4 v1 = ((const float4*)Z)[i * 2 + 1];
    float4 sc0 = *(const float4*)&g_SCALE[col];
    float4 sc1 = *(const float4*)&g_SCALE[col + 4];
    float4 sh0 = *(const float4*)&g_SHIFT[col];
    float4 sh1 = *(const float4*)&g_SHIFT[col + 4];
    __half2 o[4];
    o[0] = __floats2half2_rn(fmaxf(0.f, fmaf(v0.x, sc0.x, sh0.x)),
                             fmaxf(0.f, fmaf(v0.y, sc0.y, sh0.y)));
    o[1] = __floats2half2_rn(fmaxf(0.f, fmaf(v0.z, sc0.z, sh0.z)),
                             fmaxf(0.f, fmaf(v0.w, sc0.w, sh0.w)));
    o[2] = __floats2half2_rn(fmaxf(0.f, fmaf(v1.x, sc1.x, sh1.x)),
                             fmaxf(0.f, fmaf(v1.y, sc1.y, sh1.y)));
    o[3] = __floats2half2_rn(fmaxf(0.f, fmaf(v1.z, sc1.z, sh1.z)),
                             fmaxf(0.f, fmaf(v1.w, sc1.w, sh1.w)));
    ((uint4*)Ao)[i] = *(uint4*)o;
}

// ---------------------------------------------------------------------------
// Fused BN+ReLU+GEMV head over fp16 raw preacts Z2:
//   out[b] = sum_k relu(Z2[b,k]*sc[k]+sh[k]) * Wout[k] + bout
// ---------------------------------------------------------------------------
__global__ void __launch_bounds__(256) out_bn_gemv_kernel(
    const __half* __restrict__ Z2, const float* __restrict__ Wout,
    const float* __restrict__ bout, float* __restrict__ out)
{
    __shared__ float w[D3], sc[D3], sh[D3];
    int tid = threadIdx.x;
    ((float4*)w)[tid]  = ((const float4*)Wout)[tid];
    ((float4*)sc)[tid] = ((const float4*)g_SCALE)[tid];
    ((float4*)sh)[tid] = ((const float4*)g_SHIFT)[tid];
    __syncthreads();
    int warp = tid >> 5, lane = tid & 31;
    int b = blockIdx.x * 8 + warp;
    const __half* a = Z2 + (size_t)b * D3;
    float sum = 0.0f;
    #pragma unroll
    for (int it = 0; it < 4; it++) {
        int k = it * 256 + lane * 8;
        uint4 zv = *(const uint4*)(a + k);
        const __half2* h = (const __half2*)&zv;
        #pragma unroll
        for (int j = 0; j < 4; j++) {
            float2 f = __half22float2(h[j]);
            int kk = k + j * 2;
            float y0 = fmaxf(0.0f, fmaf(f.x, sc[kk + 0], sh[kk + 0]));
            float y1 = fmaxf(0.0f, fmaf(f.y, sc[kk + 1], sh[kk + 1]));
            sum = fmaf(y0, w[kk + 0], sum);
            sum = fmaf(y1, w[kk + 1], sum);
        }
    }
    #pragma unroll
    for (int off = 16; off > 0; off >>= 1) sum += __shfl_down_sync(0xFFFFFFFFu, sum, off);
    if (lane == 0) out[b] = sum + bout[0];
}

// ---------------------------------------------------------------------------
// Host launcher. Inputs: 0 xv, 1 W0, 2 b0, 3 g0, 4 be0, 5 W1, 6 b1, 7 g1,
// 8 be1, 9 W2, 10 b2, 11 g2, 12 be2, 13 Wout, 14 bout.
// b0/b1/b2 are absorbed by train-mode BatchNorm and never read.
// Weight conversions run on a forked side stream (graph fork/join via events)
// so convert_w0 overlaps build_h0 and convert_w1/w2 overlap the L0 GEMM.
// ---------------------------------------------------------------------------
extern "C" void kernel_launch(void* const* d_in, const int* in_sizes, int n_in,
                              void* d_out, int out_size)
{
    const float* xv   = (const float*)d_in[0];
    const float* W0   = (const float*)d_in[1];
    const float* g0   = (const float*)d_in[3];
    const float* be0  = (const float*)d_in[4];
    const float* W1   = (const float*)d_in[5];
    const float* g1   = (const float*)d_in[7];
    const float* be1  = (const float*)d_in[8];
    const float* W2   = (const float*)d_in[9];
    const float* g2   = (const float*)d_in[11];
    const float* be2  = (const float*)d_in[12];
    const float* Wout = (const float*)d_in[13];
    const float* bout = (const float*)d_in[14];
    float* out = (float*)d_out;

    cudaFuncSetAttribute(gemm_f16_kernel<float>,  cudaFuncAttributeMaxDynamicSharedMemorySize, GEMM_SMEM);
    cudaFuncSetAttribute(gemm_f16_kernel<__half>, cudaFuncAttributeMaxDynamicSharedMemorySize, GEMM_SMEM);

    __half *H0, *Ap, *Z2, *W0h, *W1h, *W2h;
    float *Z;
    cudaGetSymbolAddress((void**)&H0,  g_H0);
    cudaGetSymbolAddress((void**)&Ap,  g_A);
    cudaGetSymbolAddress((void**)&Z,   g_Z);
    cudaGetSymbolAddress((void**)&Z2,  g_Z2);
    cudaGetSymbolAddress((void**)&W0h, g_W0);
    cudaGetSymbolAddress((void**)&W1h, g_W1);
    cudaGetSymbolAddress((void**)&W2h, g_W2);

    // persistent side stream + events (host objects; created once, reused)
    static cudaStream_t s2 = nullptr;
    static cudaEvent_t eFork = nullptr, eW0 = nullptr, eW12 = nullptr;
    if (s2 == nullptr) {
        cudaStreamCreateWithFlags(&s2, cudaStreamNonBlocking);
        cudaEventCreateWithFlags(&eFork, cudaEventDisableTiming);
        cudaEventCreateWithFlags(&eW0,   cudaEventDisableTiming);
        cudaEventCreateWithFlags(&eW12,  cudaEventDisableTiming);
    }

    // ---- fork: weight conversions on s2 ----
    cudaEventRecord(eFork, 0);
    cudaStreamWaitEvent(s2, eFork, 0);
    convert_w_kernel<<<(int)(((size_t)D1 * K0P / 8 + 255) / 256), 256, 0, s2>>>(W0, W0h, D1, K0, K0P);
    cudaEventRecord(eW0, s2);
    convert_w_kernel<<<(int)(((size_t)D2 * D1 / 8 + 255) / 256), 256, 0, s2>>>(W1, W1h, D2, D1, D1);
    convert_w_kernel<<<(int)(((size_t)D3 * D2 / 8 + 255) / 256), 256, 0, s2>>>(W2, W2h, D3, D2, D2);
    cudaEventRecord(eW12, s2);

    // ---- main stream: frontend (overlaps convert_w0) ----
    build_pairs_kernel<<<8, 256>>>();
    build_h0_kernel<<<BATCH, 256>>>(xv);

    // join W0 before layer 0
    cudaStreamWaitEvent(0, eW0, 0);

    // layer 0: Z = H0 @ W0^T (fp32, stats fused) -> BN+ReLU -> fp16 A
    gemm_f16_kernel<float><<<dim3(D1 / 128, BATCH / 128), 128, GEMM_SMEM>>>(H0, W0h, Z, BATCH, D1, K0P);
    bn_finalize_kernel<<<D1 / 256, 256>>>(g0, be0, D1);
    bn_relu_half_kernel<<<(BATCH * D1 / 8) / 256, 256>>>(Z, Ap, D1, BATCH * D1 / 8);

    // join W1/W2 before layer 1 (they overlapped the L0 GEMM)
    cudaStreamWaitEvent(0, eW12, 0);

    // layer 1: Z = A @ W1^T (fp32, stats fused) -> BN+ReLU -> fp16 A
    gemm_f16_kernel<float><<<dim3(D2 / 128, BATCH / 128), 128, GEMM_SMEM>>>(Ap, W1h, Z, BATCH, D2, D1);
    bn_finalize_kernel<<<D2 / 256, 256>>>(g1, be1, D2);
    bn_relu_half_kernel<<<(BATCH * D2 / 8) / 256, 256>>>(Z, Ap, D2, BATCH * D2 / 8);

    // layer 2: Z2 = A @ W2^T (fp16 out, stats fused) — BN folded into the head
    gemm_f16_kernel<__half><<<dim3(D3 / 128, BATCH / 128), 128, GEMM_SMEM>>>(Ap, W2h, Z2, BATCH, D3, D2);
    bn_finalize_kernel<<<D3 / 256, 256>>>(g2, be2, D3);

    // fused BN2+ReLU+GEMV head
    out_bn_gemv_kernel<<<BATCH / 8, 256>>>(Z2, Wout, bout, out);
}